// round 10
// baseline (speedup 1.0000x reference)
#include <cuda_runtime.h>
#include <cuda_bf16.h>
#include <cuda_fp16.h>
#include <cstdint>
#include <cstddef>

#define NN 8192
#define MM 20000
#define DD 1024
#define YY 256

#define ST 80  // padded SMEM row stride in bytes (64B data + 16B pad)

// Scratch (no cudaMalloc allowed)
__device__ __half g_kh[(size_t)NN * (size_t)MM];     // fp16 kernel matrix
__device__ __half g_wth[(size_t)YY * (size_t)MM];    // W^T fp16
__device__ float g_xsq[NN];
__device__ float g_zsq[MM];
__device__ __nv_bfloat16 g_abf[(size_t)NN * DD];
__device__ __nv_bfloat16 g_bbf[(size_t)MM * DD];

// ---------------- helpers ----------------
__device__ __forceinline__ uint32_t s2u(const void* p) {
    return (uint32_t)__cvta_generic_to_shared(p);
}
__device__ __forceinline__ float ex2_ap(float x) {
    float r; asm("ex2.approx.f32 %0, %1;" : "=f"(r) : "f"(x)); return r;
}
__device__ __forceinline__ float sqrt_ap(float x) {
    float r; asm("sqrt.approx.f32 %0, %1;" : "=f"(r) : "f"(x)); return r;
}
__device__ __forceinline__ void cp16(uint32_t dst, const void* src) {
    asm volatile("cp.async.cg.shared.global [%0], [%1], 16;" :: "r"(dst), "l"(src));
}
__device__ __forceinline__ void cp_commit() {
    asm volatile("cp.async.commit_group;" ::: "memory");
}
template <int N>
__device__ __forceinline__ void cp_wait() {
    asm volatile("cp.async.wait_group %0;" :: "n"(N) : "memory");
}
__device__ __forceinline__ void ldm_x4(uint32_t& r0, uint32_t& r1, uint32_t& r2,
                                       uint32_t& r3, uint32_t addr) {
    asm volatile("ldmatrix.sync.aligned.m8n8.x4.shared.b16 {%0,%1,%2,%3}, [%4];"
                 : "=r"(r0), "=r"(r1), "=r"(r2), "=r"(r3) : "r"(addr));
}
__device__ __forceinline__ void ldm_x2(uint32_t& r0, uint32_t& r1, uint32_t addr) {
    asm volatile("ldmatrix.sync.aligned.m8n8.x2.shared.b16 {%0,%1}, [%2];"
                 : "=r"(r0), "=r"(r1) : "r"(addr));
}
__device__ __forceinline__ void mma_bf16(float* c, uint32_t a0, uint32_t a1,
                                         uint32_t a2, uint32_t a3,
                                         uint32_t b0, uint32_t b1) {
    asm volatile(
        "mma.sync.aligned.m16n8k16.row.col.f32.bf16.bf16.f32 "
        "{%0,%1,%2,%3}, {%4,%5,%6,%7}, {%8,%9}, {%0,%1,%2,%3};"
        : "+f"(c[0]), "+f"(c[1]), "+f"(c[2]), "+f"(c[3])
        : "r"(a0), "r"(a1), "r"(a2), "r"(a3), "r"(b0), "r"(b1));
}
__device__ __forceinline__ void mma_f16(float* c, uint32_t a0, uint32_t a1,
                                        uint32_t a2, uint32_t a3,
                                        uint32_t b0, uint32_t b1) {
    asm volatile(
        "mma.sync.aligned.m16n8k16.row.col.f32.f16.f16.f32 "
        "{%0,%1,%2,%3}, {%4,%5,%6,%7}, {%8,%9}, {%0,%1,%2,%3};"
        : "+f"(c[0]), "+f"(c[1]), "+f"(c[2]), "+f"(c[3])
        : "r"(a0), "r"(a1), "r"(a2), "r"(a3), "r"(b0), "r"(b1));
}

// ---- fused fp32->bf16 conversion + row squared-norm (one pass) ----
__global__ void cvtnorm_kernel(const float* __restrict__ src,
                               __nv_bfloat16* __restrict__ dst,
                               float* __restrict__ nrm) {
    int row = blockIdx.x;
    const float4* p = reinterpret_cast<const float4*>(src + (size_t)row * DD);
    float4 v = p[threadIdx.x];  // 256 threads x float4 = 1024 elems
    __nv_bfloat162 lo = __floats2bfloat162_rn(v.x, v.y);
    __nv_bfloat162 hi = __floats2bfloat162_rn(v.z, v.w);
    uint2 o;
    o.x = *reinterpret_cast<unsigned*>(&lo);
    o.y = *reinterpret_cast<unsigned*>(&hi);
    reinterpret_cast<uint2*>(dst + (size_t)row * DD)[threadIdx.x] = o;

    float s = fmaf(v.x, v.x, fmaf(v.y, v.y, fmaf(v.z, v.z, v.w * v.w)));
#pragma unroll
    for (int off = 16; off; off >>= 1) s += __shfl_xor_sync(0xffffffffu, s, off);
    __shared__ float ws[8];
    int lane = threadIdx.x & 31, w = threadIdx.x >> 5;
    if (lane == 0) ws[w] = s;
    __syncthreads();
    if (threadIdx.x == 0) {
        float t = 0.f;
#pragma unroll
        for (int i = 0; i < 8; ++i) t += ws[i];
        nrm[row] = t;
    }
}

// ---- transpose W [MM][YY] -> Wt [YY][MM] in fp16 ----
__global__ void wth_kernel(const float* __restrict__ W) {
    __shared__ float t[32][33];
    int bx = blockIdx.x * 32;  // y block
    int by = blockIdx.y * 32;  // m block
    int tx = threadIdx.x, ty = threadIdx.y;
#pragma unroll
    for (int q = 0; q < 4; ++q)
        t[ty + q * 8][tx] = W[(size_t)(by + ty + q * 8) * YY + bx + tx];
    __syncthreads();
#pragma unroll
    for (int q = 0; q < 4; ++q) {
        float v = t[tx][ty + q * 8];
        g_wth[(size_t)(bx + ty + q * 8) * MM + by + tx] = __float2half_rn(v);
    }
}

// ============== GEMM1: bf16 mma.sync, fused Laplacian epilogue ==============
// 128(n) x 256(m) x 32 tile, 256 threads, 8 warps (2x4), warp tile 64x64,
// 3 stages. Arithmetic-intensity raised to beat the L2->SMEM bandwidth wall.
#define NCH1 32
#define S1A (128 * ST)      // 10240
#define S1B (256 * ST)      // 20480
#define S1 (S1A + S1B)      // 30720 per stage
#define SMEM1 (3 * S1)      // 92160

__device__ __forceinline__ void g1_copy(uint32_t stage, int kc,
                                        int tid, int nBase, int mBase) {
    // A: 128 rows x 64B; 2 threads per row
    {
        int row = tid >> 1;
        int s0 = (tid & 1) * 2;
        const char* asrc = reinterpret_cast<const char*>(g_abf) +
                           ((size_t)(nBase + row) * DD + (size_t)kc * 32) * 2;
        uint32_t ad = stage + row * ST;
        cp16(ad + s0 * 16, asrc + s0 * 16);
        cp16(ad + (s0 + 1) * 16, asrc + (s0 + 1) * 16);
    }
    // B: 256 rows x 64B; 1 thread per row, 4 cp16
    {
        int gm = mBase + tid;
        if (gm >= MM) gm = MM - 1;
        const char* bsrc = reinterpret_cast<const char*>(g_bbf) +
                           ((size_t)gm * DD + (size_t)kc * 32) * 2;
        uint32_t bd = stage + S1A + tid * ST;
#pragma unroll
        for (int s = 0; s < 4; ++s) cp16(bd + s * 16, bsrc + s * 16);
    }
    cp_commit();
}

__global__ __launch_bounds__(256)
void kmat_mma_kernel(const int* __restrict__ bwp) {
    extern __shared__ __align__(16) char sm1[];

    const int tid = threadIdx.x;
    const int l = tid & 31;
    const int wid = tid >> 5;
    const int wr = wid >> 2;   // 0..1 (n)
    const int wc = wid & 3;    // 0..3 (m)

    // CTA swizzle: groups of 8 n-blocks for L2 reuse
    const int GM = (MM + 255) / 256;  // 79 m-blocks
    int bid = blockIdx.x;
    int grp = bid / (8 * GM);
    int rem = bid % (8 * GM);
    const int nBase = (grp * 8 + (rem & 7)) * 128;
    const int mBase = (rem >> 3) * 256;

    const uint32_t base = s2u(sm1);

    float c[4][8][4];
#pragma unroll
    for (int i = 0; i < 4; ++i)
#pragma unroll
        for (int j = 0; j < 8; ++j)
#pragma unroll
            for (int q = 0; q < 4; ++q) c[i][j][q] = 0.f;

    g1_copy(base + 0 * S1, 0, tid, nBase, mBase);
    g1_copy(base + 1 * S1, 1, tid, nBase, mBase);

    for (int kc = 0; kc < NCH1; ++kc) {
        if (kc < NCH1 - 1) cp_wait<1>(); else cp_wait<0>();
        __syncthreads();
        if (kc + 2 < NCH1)
            g1_copy(base + (uint32_t)((kc + 2) % 3) * S1, kc + 2, tid, nBase, mBase);

        uint32_t aS = base + (uint32_t)(kc % 3) * S1;
        uint32_t bS = aS + S1A;
#pragma unroll
        for (int ks = 0; ks < 2; ++ks) {
            int koff = ks * 32;
            uint32_t a[4][4];
#pragma unroll
            for (int i = 0; i < 4; ++i)
                ldm_x4(a[i][0], a[i][1], a[i][2], a[i][3],
                       aS + (wr * 64 + i * 16 + (l & 15)) * ST + koff + ((l >> 4) << 4));
            uint32_t b[8][2];
#pragma unroll
            for (int j = 0; j < 8; ++j)
                ldm_x2(b[j][0], b[j][1],
                       bS + (wc * 64 + j * 8 + (l & 7)) * ST + koff + (((l >> 3) & 1) << 4));
#pragma unroll
            for (int i = 0; i < 4; ++i)
#pragma unroll
                for (int j = 0; j < 8; ++j)
                    mma_bf16(c[i][j], a[i][0], a[i][1], a[i][2], a[i][3],
                             b[j][0], b[j][1]);
        }
    }

    // ---- epilogue: exp(-sqrt(|x|^2+|z|^2-2 dot)/bw) -> fp16 kmat ----
    int ibw = *bwp;
    float bwf = (ibw > 0 && ibw < 1000000) ? (float)ibw : __int_as_float(ibw);
    const float negscale = -1.44269504088896f / bwf;

#pragma unroll
    for (int i = 0; i < 4; ++i) {
        int r0 = nBase + wr * 64 + i * 16 + (l >> 2);
        float xs0 = g_xsq[r0];
        float xs1 = g_xsq[r0 + 8];
#pragma unroll
        for (int j = 0; j < 8; ++j) {
            int col = mBase + wc * 64 + j * 8 + 2 * (l & 3);
            if (col < MM) {  // MM even; a half2 never straddles the edge
                float2 zz = *reinterpret_cast<const float2*>(&g_zsq[col]);
                float d00 = fmaf(-2.f, c[i][j][0], xs0 + zz.x);
                float d01 = fmaf(-2.f, c[i][j][1], xs0 + zz.y);
                float d10 = fmaf(-2.f, c[i][j][2], xs1 + zz.x);
                float d11 = fmaf(-2.f, c[i][j][3], xs1 + zz.y);
                float v00 = ex2_ap(sqrt_ap(fmaxf(d00, 0.f)) * negscale);
                float v01 = ex2_ap(sqrt_ap(fmaxf(d01, 0.f)) * negscale);
                float v10 = ex2_ap(sqrt_ap(fmaxf(d10, 0.f)) * negscale);
                float v11 = ex2_ap(sqrt_ap(fmaxf(d11, 0.f)) * negscale);
                *reinterpret_cast<__half2*>(g_kh + (size_t)r0 * MM + col) =
                    __floats2half2_rn(v00, v01);
                *reinterpret_cast<__half2*>(g_kh + (size_t)(r0 + 8) * MM + col) =
                    __floats2half2_rn(v10, v11);
            }
        }
    }
}

// ============== GEMM2: fp16 mma.sync out = kmat @ W ==============
// 64n x 256y tile, BK=32, 256 threads, 8 warps (2x4), warp 32x64, 4 stages.
#define NCH2 (MM / 32)              // 625
#define S2 ((64 + 256) * ST)        // 25600 B per stage
#define SMEM2 (4 * S2)              // 102400 B

__device__ __forceinline__ void g2_copy(uint32_t stage, int kc,
                                        int tid, int nBase) {
    int s = tid & 3;
    {
        int row = tid >> 2;  // 0..63
        const char* asrc = reinterpret_cast<const char*>(g_kh) +
                           ((size_t)(nBase + row) * MM + (size_t)kc * 32) * 2;
        cp16(stage + row * ST + s * 16, asrc + s * 16);
    }
#pragma unroll
    for (int i = 0; i < 4; ++i) {
        int row = (tid >> 2) + i * 64;  // 0..255 (y)
        const char* bsrc = reinterpret_cast<const char*>(g_wth) +
                           ((size_t)row * MM + (size_t)kc * 32) * 2;
        cp16(stage + 64 * ST + row * ST + s * 16, bsrc + s * 16);
    }
    cp_commit();
}

__global__ __launch_bounds__(256)
void out_mma_kernel(float* __restrict__ Out) {
    extern __shared__ __align__(16) char sm2[];

    const int tid = threadIdx.x;
    const int l = tid & 31;
    const int wid = tid >> 5;
    const int wr = wid >> 2;   // 0..1 (n)
    const int wc = wid & 3;    // 0..3 (y)
    const int nBase = blockIdx.x * 64;
    const uint32_t base = s2u(sm2);

    float c[2][8][4];
#pragma unroll
    for (int i = 0; i < 2; ++i)
#pragma unroll
        for (int j = 0; j < 8; ++j)
#pragma unroll
            for (int q = 0; q < 4; ++q) c[i][j][q] = 0.f;

    g2_copy(base + 0 * S2, 0, tid, nBase);
    g2_copy(base + 1 * S2, 1, tid, nBase);
    g2_copy(base + 2 * S2, 2, tid, nBase);

    for (int kc = 0; kc < NCH2; ++kc) {
        if (kc < NCH2 - 2) cp_wait<2>();
        else if (kc == NCH2 - 2) cp_wait<1>();
        else cp_wait<0>();
        __syncthreads();
        if (kc + 3 < NCH2)
            g2_copy(base + (uint32_t)((kc + 3) & 3) * S2, kc + 3, tid, nBase);

        uint32_t aS = base + (uint32_t)(kc & 3) * S2;
        uint32_t bS = aS + 64 * ST;
#pragma unroll
        for (int ks = 0; ks < 2; ++ks) {
            int koff = ks * 32;
            uint32_t a[2][4];
#pragma unroll
            for (int i = 0; i < 2; ++i)
                ldm_x4(a[i][0], a[i][1], a[i][2], a[i][3],
                       aS + (wr * 32 + i * 16 + (l & 15)) * ST + koff + ((l >> 4) << 4));
            uint32_t b[8][2];
#pragma unroll
            for (int j = 0; j < 8; ++j)
                ldm_x2(b[j][0], b[j][1],
                       bS + (wc * 64 + j * 8 + (l & 7)) * ST + koff + (((l >> 3) & 1) << 4));
#pragma unroll
            for (int i = 0; i < 2; ++i)
#pragma unroll
                for (int j = 0; j < 8; ++j)
                    mma_f16(c[i][j], a[i][0], a[i][1], a[i][2], a[i][3],
                            b[j][0], b[j][1]);
        }
    }

#pragma unroll
    for (int i = 0; i < 2; ++i) {
        int r0 = nBase + wr * 32 + i * 16 + (l >> 2);
#pragma unroll
        for (int j = 0; j < 8; ++j) {
            int col = wc * 64 + j * 8 + 2 * (l & 3);
            *reinterpret_cast<float2*>(Out + (size_t)r0 * YY + col) =
                make_float2(c[i][j][0], c[i][j][1]);
            *reinterpret_cast<float2*>(Out + (size_t)(r0 + 8) * YY + col) =
                make_float2(c[i][j][2], c[i][j][3]);
        }
    }
}

extern "C" void kernel_launch(void* const* d_in, const int* in_sizes, int n_in,
                              void* d_out, int out_size) {
    (void)in_sizes; (void)n_in; (void)out_size;
    const float* batch   = (const float*)d_in[0];
    const float* centers = (const float*)d_in[1];
    const float* weight  = (const float*)d_in[2];
    const int*   bwp     = (const int*)d_in[3];
    float* out = (float*)d_out;

    cudaFuncSetAttribute(kmat_mma_kernel,
                         cudaFuncAttributeMaxDynamicSharedMemorySize, SMEM1);
    cudaFuncSetAttribute(out_mma_kernel,
                         cudaFuncAttributeMaxDynamicSharedMemorySize, SMEM2);

    __nv_bfloat16* abf_p = nullptr;
    __nv_bfloat16* bbf_p = nullptr;
    float* xsq_p = nullptr;
    float* zsq_p = nullptr;
    cudaGetSymbolAddress((void**)&abf_p, g_abf);
    cudaGetSymbolAddress((void**)&bbf_p, g_bbf);
    cudaGetSymbolAddress((void**)&xsq_p, g_xsq);
    cudaGetSymbolAddress((void**)&zsq_p, g_zsq);

    cvtnorm_kernel<<<NN, 256>>>(batch, abf_p, xsq_p);
    cvtnorm_kernel<<<MM, 256>>>(centers, bbf_p, zsq_p);

    {
        dim3 b(32, 8);
        dim3 g(YY / 32, MM / 32);  // 8 x 625
        wth_kernel<<<g, b>>>(weight);
    }

    const int GM = (MM + 255) / 256;           // 79
    kmat_mma_kernel<<<GM * (NN / 128), 256, SMEM1>>>(bwp);

    out_mma_kernel<<<NN / 64, 256, SMEM2>>>(out);
}

// round 11
// speedup vs baseline: 1.1715x; 1.1715x over previous
#include <cuda_runtime.h>
#include <cuda_bf16.h>
#include <cuda_fp16.h>
#include <cstdint>
#include <cstddef>

#define NN 8192
#define MM 20000
#define DD 1024
#define YY 256

#define ST 80    // GEMM2 SMEM row stride (64B data + 16B pad)
#define ST1 144  // GEMM1 SMEM row stride (128B data + 16B pad)

// Scratch (no cudaMalloc allowed)
__device__ __half g_kh[(size_t)NN * (size_t)MM];     // fp16 kernel matrix
__device__ __half g_wth[(size_t)YY * (size_t)MM];    // W^T fp16
__device__ float g_xsq[NN];
__device__ float g_zsq[MM];
__device__ __nv_bfloat16 g_abf[(size_t)NN * DD];
__device__ __nv_bfloat16 g_bbf[(size_t)MM * DD];

// ---------------- helpers ----------------
__device__ __forceinline__ uint32_t s2u(const void* p) {
    return (uint32_t)__cvta_generic_to_shared(p);
}
__device__ __forceinline__ float ex2_ap(float x) {
    float r; asm("ex2.approx.f32 %0, %1;" : "=f"(r) : "f"(x)); return r;
}
__device__ __forceinline__ float sqrt_ap(float x) {
    float r; asm("sqrt.approx.f32 %0, %1;" : "=f"(r) : "f"(x)); return r;
}
__device__ __forceinline__ void cp16(uint32_t dst, const void* src) {
    asm volatile("cp.async.cg.shared.global [%0], [%1], 16;" :: "r"(dst), "l"(src));
}
__device__ __forceinline__ void cp_commit() {
    asm volatile("cp.async.commit_group;" ::: "memory");
}
template <int N>
__device__ __forceinline__ void cp_wait() {
    asm volatile("cp.async.wait_group %0;" :: "n"(N) : "memory");
}
__device__ __forceinline__ void ldm_x4(uint32_t& r0, uint32_t& r1, uint32_t& r2,
                                       uint32_t& r3, uint32_t addr) {
    asm volatile("ldmatrix.sync.aligned.m8n8.x4.shared.b16 {%0,%1,%2,%3}, [%4];"
                 : "=r"(r0), "=r"(r1), "=r"(r2), "=r"(r3) : "r"(addr));
}
__device__ __forceinline__ void ldm_x2(uint32_t& r0, uint32_t& r1, uint32_t addr) {
    asm volatile("ldmatrix.sync.aligned.m8n8.x2.shared.b16 {%0,%1}, [%2];"
                 : "=r"(r0), "=r"(r1) : "r"(addr));
}
__device__ __forceinline__ void mma_bf16(float* c, uint32_t a0, uint32_t a1,
                                         uint32_t a2, uint32_t a3,
                                         uint32_t b0, uint32_t b1) {
    asm volatile(
        "mma.sync.aligned.m16n8k16.row.col.f32.bf16.bf16.f32 "
        "{%0,%1,%2,%3}, {%4,%5,%6,%7}, {%8,%9}, {%0,%1,%2,%3};"
        : "+f"(c[0]), "+f"(c[1]), "+f"(c[2]), "+f"(c[3])
        : "r"(a0), "r"(a1), "r"(a2), "r"(a3), "r"(b0), "r"(b1));
}
__device__ __forceinline__ void mma_f16(float* c, uint32_t a0, uint32_t a1,
                                        uint32_t a2, uint32_t a3,
                                        uint32_t b0, uint32_t b1) {
    asm volatile(
        "mma.sync.aligned.m16n8k16.row.col.f32.f16.f16.f32 "
        "{%0,%1,%2,%3}, {%4,%5,%6,%7}, {%8,%9}, {%0,%1,%2,%3};"
        : "+f"(c[0]), "+f"(c[1]), "+f"(c[2]), "+f"(c[3])
        : "r"(a0), "r"(a1), "r"(a2), "r"(a3), "r"(b0), "r"(b1));
}

// ---- fused fp32->bf16 conversion + row squared-norm (one pass) ----
__global__ void cvtnorm_kernel(const float* __restrict__ src,
                               __nv_bfloat16* __restrict__ dst,
                               float* __restrict__ nrm) {
    int row = blockIdx.x;
    const float4* p = reinterpret_cast<const float4*>(src + (size_t)row * DD);
    float4 v = p[threadIdx.x];  // 256 threads x float4 = 1024 elems
    __nv_bfloat162 lo = __floats2bfloat162_rn(v.x, v.y);
    __nv_bfloat162 hi = __floats2bfloat162_rn(v.z, v.w);
    uint2 o;
    o.x = *reinterpret_cast<unsigned*>(&lo);
    o.y = *reinterpret_cast<unsigned*>(&hi);
    reinterpret_cast<uint2*>(dst + (size_t)row * DD)[threadIdx.x] = o;

    float s = fmaf(v.x, v.x, fmaf(v.y, v.y, fmaf(v.z, v.z, v.w * v.w)));
#pragma unroll
    for (int off = 16; off; off >>= 1) s += __shfl_xor_sync(0xffffffffu, s, off);
    __shared__ float ws[8];
    int lane = threadIdx.x & 31, w = threadIdx.x >> 5;
    if (lane == 0) ws[w] = s;
    __syncthreads();
    if (threadIdx.x == 0) {
        float t = 0.f;
#pragma unroll
        for (int i = 0; i < 8; ++i) t += ws[i];
        nrm[row] = t;
    }
}

// ---- transpose W [MM][YY] -> Wt [YY][MM] in fp16 ----
__global__ void wth_kernel(const float* __restrict__ W) {
    __shared__ float t[32][33];
    int bx = blockIdx.x * 32;  // y block
    int by = blockIdx.y * 32;  // m block
    int tx = threadIdx.x, ty = threadIdx.y;
#pragma unroll
    for (int q = 0; q < 4; ++q)
        t[ty + q * 8][tx] = W[(size_t)(by + ty + q * 8) * YY + bx + tx];
    __syncthreads();
#pragma unroll
    for (int q = 0; q < 4; ++q) {
        float v = t[tx][ty + q * 8];
        g_wth[(size_t)(bx + ty + q * 8) * MM + by + tx] = __float2half_rn(v);
    }
}

// ============== GEMM1: bf16 mma.sync, fused Laplacian epilogue ==============
// 128x128x64 tile, 256 threads, 8 warps (2x4), warp tile 64x32, 3 stages.
// BK=64 halves barrier count vs BK=32; B fragments via paired ldmatrix.x4.
#define NCH1 (DD / 64)      // 16
#define S1A (128 * ST1)     // 18432
#define S1 (2 * S1A)        // 36864 per stage (A+B)
#define SMEM1 (3 * S1)      // 110592 -> 2 CTAs = 216KB < 228KB SM capacity

__device__ __forceinline__ void g1_copy(uint32_t stage, int kc,
                                        int tid, int nBase, int mBase) {
    int row = tid >> 1;
    int s0 = (tid & 1) * 4;  // first 16B segment (of 8 per 128B row)
    const char* asrc = reinterpret_cast<const char*>(g_abf) +
                       ((size_t)(nBase + row) * DD + (size_t)kc * 64) * 2 + s0 * 16;
    uint32_t ad = stage + row * ST1 + s0 * 16;
#pragma unroll
    for (int s = 0; s < 4; ++s) cp16(ad + s * 16, asrc + s * 16);

    int gm = mBase + row;
    if (gm >= MM) gm = MM - 1;  // clamp; epilogue masks stores
    const char* bsrc = reinterpret_cast<const char*>(g_bbf) +
                       ((size_t)gm * DD + (size_t)kc * 64) * 2 + s0 * 16;
    uint32_t bd = stage + S1A + row * ST1 + s0 * 16;
#pragma unroll
    for (int s = 0; s < 4; ++s) cp16(bd + s * 16, bsrc + s * 16);
    cp_commit();
}

__global__ __launch_bounds__(256, 2)
void kmat_mma_kernel(const int* __restrict__ bwp) {
    extern __shared__ __align__(16) char sm1[];

    const int tid = threadIdx.x;
    const int l = tid & 31;
    const int wid = tid >> 5;
    const int wr = wid >> 2;   // 0..1 (n)
    const int wc = wid & 3;    // 0..3 (m)

    // CTA swizzle: groups of 8 n-blocks for L2 reuse
    const int GM = (MM + 127) / 128;  // 157 m-blocks
    int bid = blockIdx.x;
    int grp = bid / (8 * GM);
    int rem = bid % (8 * GM);
    const int nBase = (grp * 8 + (rem & 7)) * 128;
    const int mBase = (rem >> 3) * 128;

    const uint32_t base = s2u(sm1);

    float c[4][4][4];
#pragma unroll
    for (int i = 0; i < 4; ++i)
#pragma unroll
        for (int j = 0; j < 4; ++j)
#pragma unroll
            for (int q = 0; q < 4; ++q) c[i][j][q] = 0.f;

    g1_copy(base + 0 * S1, 0, tid, nBase, mBase);
    g1_copy(base + 1 * S1, 1, tid, nBase, mBase);

    for (int kc = 0; kc < NCH1; ++kc) {
        if (kc < NCH1 - 1) cp_wait<1>(); else cp_wait<0>();
        __syncthreads();
        if (kc + 2 < NCH1)
            g1_copy(base + (uint32_t)((kc + 2) % 3) * S1, kc + 2, tid, nBase, mBase);

        uint32_t aS = base + (uint32_t)(kc % 3) * S1;
        uint32_t bS = aS + S1A;
#pragma unroll
        for (int ks = 0; ks < 4; ++ks) {
            int koff = ks * 32;
            uint32_t a[4][4];
#pragma unroll
            for (int i = 0; i < 4; ++i)
                ldm_x4(a[i][0], a[i][1], a[i][2], a[i][3],
                       aS + (wr * 64 + i * 16 + (l & 15)) * ST1 + koff + ((l >> 4) << 4));
            // B: two j-matrices per ldmatrix.x4 (lane groups 16-31 -> j+1)
            uint32_t b[4][2];
#pragma unroll
            for (int j2 = 0; j2 < 2; ++j2)
                ldm_x4(b[2 * j2][0], b[2 * j2][1], b[2 * j2 + 1][0], b[2 * j2 + 1][1],
                       bS + (wc * 32 + (j2 * 2 + ((l >> 4) & 1)) * 8 + (l & 7)) * ST1 +
                           koff + (((l >> 3) & 1) << 4));
#pragma unroll
            for (int i = 0; i < 4; ++i)
#pragma unroll
                for (int j = 0; j < 4; ++j)
                    mma_bf16(c[i][j], a[i][0], a[i][1], a[i][2], a[i][3],
                             b[j][0], b[j][1]);
        }
    }

    // ---- epilogue: exp(-sqrt(|x|^2+|z|^2-2 dot)/bw) -> fp16 kmat ----
    int ibw = *bwp;
    float bwf = (ibw > 0 && ibw < 1000000) ? (float)ibw : __int_as_float(ibw);
    const float negscale = -1.44269504088896f / bwf;

#pragma unroll
    for (int i = 0; i < 4; ++i) {
        int r0 = nBase + wr * 64 + i * 16 + (l >> 2);
        float xs0 = g_xsq[r0];
        float xs1 = g_xsq[r0 + 8];
#pragma unroll
        for (int j = 0; j < 4; ++j) {
            int col = mBase + wc * 32 + j * 8 + 2 * (l & 3);
            if (col < MM) {  // MM even; a half2 never straddles the edge
                float2 zz = *reinterpret_cast<const float2*>(&g_zsq[col]);
                float d00 = fmaf(-2.f, c[i][j][0], xs0 + zz.x);
                float d01 = fmaf(-2.f, c[i][j][1], xs0 + zz.y);
                float d10 = fmaf(-2.f, c[i][j][2], xs1 + zz.x);
                float d11 = fmaf(-2.f, c[i][j][3], xs1 + zz.y);
                float v00 = ex2_ap(sqrt_ap(fmaxf(d00, 0.f)) * negscale);
                float v01 = ex2_ap(sqrt_ap(fmaxf(d01, 0.f)) * negscale);
                float v10 = ex2_ap(sqrt_ap(fmaxf(d10, 0.f)) * negscale);
                float v11 = ex2_ap(sqrt_ap(fmaxf(d11, 0.f)) * negscale);
                *reinterpret_cast<__half2*>(g_kh + (size_t)r0 * MM + col) =
                    __floats2half2_rn(v00, v01);
                *reinterpret_cast<__half2*>(g_kh + (size_t)(r0 + 8) * MM + col) =
                    __floats2half2_rn(v10, v11);
            }
        }
    }
}

// ============== GEMM2: fp16 mma.sync out = kmat @ W ==============
// 64n x 256y tile, BK=32, 256 threads, 8 warps (2x4), warp 32x64, 4 stages.
#define NCH2 (MM / 32)              // 625
#define S2 ((64 + 256) * ST)        // 25600 B per stage
#define SMEM2 (4 * S2)              // 102400 B

__device__ __forceinline__ void g2_copy(uint32_t stage, int kc,
                                        int tid, int nBase) {
    int s = tid & 3;
    {
        int row = tid >> 2;  // 0..63
        const char* asrc = reinterpret_cast<const char*>(g_kh) +
                           ((size_t)(nBase + row) * MM + (size_t)kc * 32) * 2;
        cp16(stage + row * ST + s * 16, asrc + s * 16);
    }
#pragma unroll
    for (int i = 0; i < 4; ++i) {
        int row = (tid >> 2) + i * 64;  // 0..255 (y)
        const char* bsrc = reinterpret_cast<const char*>(g_wth) +
                           ((size_t)row * MM + (size_t)kc * 32) * 2;
        cp16(stage + 64 * ST + row * ST + s * 16, bsrc + s * 16);
    }
    cp_commit();
}

__global__ __launch_bounds__(256)
void out_mma_kernel(float* __restrict__ Out) {
    extern __shared__ __align__(16) char sm2[];

    const int tid = threadIdx.x;
    const int l = tid & 31;
    const int wid = tid >> 5;
    const int wr = wid >> 2;   // 0..1 (n)
    const int wc = wid & 3;    // 0..3 (y)
    const int nBase = blockIdx.x * 64;
    const uint32_t base = s2u(sm2);

    float c[2][8][4];
#pragma unroll
    for (int i = 0; i < 2; ++i)
#pragma unroll
        for (int j = 0; j < 8; ++j)
#pragma unroll
            for (int q = 0; q < 4; ++q) c[i][j][q] = 0.f;

    g2_copy(base + 0 * S2, 0, tid, nBase);
    g2_copy(base + 1 * S2, 1, tid, nBase);
    g2_copy(base + 2 * S2, 2, tid, nBase);

    for (int kc = 0; kc < NCH2; ++kc) {
        if (kc < NCH2 - 2) cp_wait<2>();
        else if (kc == NCH2 - 2) cp_wait<1>();
        else cp_wait<0>();
        __syncthreads();
        if (kc + 3 < NCH2)
            g2_copy(base + (uint32_t)((kc + 3) & 3) * S2, kc + 3, tid, nBase);

        uint32_t aS = base + (uint32_t)(kc & 3) * S2;
        uint32_t bS = aS + 64 * ST;
#pragma unroll
        for (int ks = 0; ks < 2; ++ks) {
            int koff = ks * 32;
            uint32_t a[2][4];
#pragma unroll
            for (int i = 0; i < 2; ++i)
                ldm_x4(a[i][0], a[i][1], a[i][2], a[i][3],
                       aS + (wr * 32 + i * 16 + (l & 15)) * ST + koff + ((l >> 4) << 4));
            uint32_t b[8][2];
#pragma unroll
            for (int j2 = 0; j2 < 4; ++j2)
                ldm_x4(b[2 * j2][0], b[2 * j2][1], b[2 * j2 + 1][0], b[2 * j2 + 1][1],
                       bS + (wc * 64 + (j2 * 2 + ((l >> 4) & 1)) * 8 + (l & 7)) * ST +
                           koff + (((l >> 3) & 1) << 4));
#pragma unroll
            for (int i = 0; i < 2; ++i)
#pragma unroll
                for (int j = 0; j < 8; ++j)
                    mma_f16(c[i][j], a[i][0], a[i][1], a[i][2], a[i][3],
                            b[j][0], b[j][1]);
        }
    }

#pragma unroll
    for (int i = 0; i < 2; ++i) {
        int r0 = nBase + wr * 32 + i * 16 + (l >> 2);
#pragma unroll
        for (int j = 0; j < 8; ++j) {
            int col = wc * 64 + j * 8 + 2 * (l & 3);
            *reinterpret_cast<float2*>(Out + (size_t)r0 * YY + col) =
                make_float2(c[i][j][0], c[i][j][1]);
            *reinterpret_cast<float2*>(Out + (size_t)(r0 + 8) * YY + col) =
                make_float2(c[i][j][2], c[i][j][3]);
        }
    }
}

extern "C" void kernel_launch(void* const* d_in, const int* in_sizes, int n_in,
                              void* d_out, int out_size) {
    (void)in_sizes; (void)n_in; (void)out_size;
    const float* batch   = (const float*)d_in[0];
    const float* centers = (const float*)d_in[1];
    const float* weight  = (const float*)d_in[2];
    const int*   bwp     = (const int*)d_in[3];
    float* out = (float*)d_out;

    cudaFuncSetAttribute(kmat_mma_kernel,
                         cudaFuncAttributeMaxDynamicSharedMemorySize, SMEM1);
    cudaFuncSetAttribute(out_mma_kernel,
                         cudaFuncAttributeMaxDynamicSharedMemorySize, SMEM2);

    __nv_bfloat16* abf_p = nullptr;
    __nv_bfloat16* bbf_p = nullptr;
    float* xsq_p = nullptr;
    float* zsq_p = nullptr;
    cudaGetSymbolAddress((void**)&abf_p, g_abf);
    cudaGetSymbolAddress((void**)&bbf_p, g_bbf);
    cudaGetSymbolAddress((void**)&xsq_p, g_xsq);
    cudaGetSymbolAddress((void**)&zsq_p, g_zsq);

    cvtnorm_kernel<<<NN, 256>>>(batch, abf_p, xsq_p);
    cvtnorm_kernel<<<MM, 256>>>(centers, bbf_p, zsq_p);

    {
        dim3 b(32, 8);
        dim3 g(YY / 32, MM / 32);  // 8 x 625
        wth_kernel<<<g, b>>>(weight);
    }

    const int GM = (MM + 127) / 128;           // 157
    kmat_mma_kernel<<<GM * (NN / 128), 256, SMEM1>>>(bwp);

    out_mma_kernel<<<NN / 64, 256, SMEM2>>>(out);
}

// round 15
// speedup vs baseline: 1.2073x; 1.0305x over previous
#include <cuda_runtime.h>
#include <cuda_bf16.h>
#include <cuda_fp16.h>
#include <cstdint>
#include <cstddef>

#define NN 8192
#define MM 20000
#define DD 1024
#define YY 256

#define ST 80    // GEMM2 SMEM row stride (64B data + 16B pad)
#define ST1 144  // GEMM1 SMEM row stride (128B data + 16B pad)

// Scratch (no cudaMalloc allowed)
__device__ __half g_kh[(size_t)NN * (size_t)MM];     // fp16 kernel matrix
__device__ __half g_wth[(size_t)YY * (size_t)MM];    // W^T fp16
__device__ float g_xsq[NN];
__device__ float g_zsq[MM];
__device__ __nv_bfloat16 g_abf[(size_t)NN * DD];
__device__ __nv_bfloat16 g_bbf[(size_t)MM * DD];

// ---------------- helpers ----------------
__device__ __forceinline__ uint32_t s2u(const void* p) {
    return (uint32_t)__cvta_generic_to_shared(p);
}
__device__ __forceinline__ float ex2_ap(float x) {
    float r; asm("ex2.approx.f32 %0, %1;" : "=f"(r) : "f"(x)); return r;
}
__device__ __forceinline__ float sqrt_ap(float x) {
    float r; asm("sqrt.approx.f32 %0, %1;" : "=f"(r) : "f"(x)); return r;
}
__device__ __forceinline__ void cp16(uint32_t dst, const void* src) {
    asm volatile("cp.async.cg.shared.global [%0], [%1], 16;" :: "r"(dst), "l"(src));
}
__device__ __forceinline__ void cp_commit() {
    asm volatile("cp.async.commit_group;" ::: "memory");
}
template <int N>
__device__ __forceinline__ void cp_wait() {
    asm volatile("cp.async.wait_group %0;" :: "n"(N) : "memory");
}
__device__ __forceinline__ void ldm_x4(uint32_t& r0, uint32_t& r1, uint32_t& r2,
                                       uint32_t& r3, uint32_t addr) {
    asm volatile("ldmatrix.sync.aligned.m8n8.x4.shared.b16 {%0,%1,%2,%3}, [%4];"
                 : "=r"(r0), "=r"(r1), "=r"(r2), "=r"(r3) : "r"(addr));
}
__device__ __forceinline__ void mma_bf16(float* c, uint32_t a0, uint32_t a1,
                                         uint32_t a2, uint32_t a3,
                                         uint32_t b0, uint32_t b1) {
    asm volatile(
        "mma.sync.aligned.m16n8k16.row.col.f32.bf16.bf16.f32 "
        "{%0,%1,%2,%3}, {%4,%5,%6,%7}, {%8,%9}, {%0,%1,%2,%3};"
        : "+f"(c[0]), "+f"(c[1]), "+f"(c[2]), "+f"(c[3])
        : "r"(a0), "r"(a1), "r"(a2), "r"(a3), "r"(b0), "r"(b1));
}
__device__ __forceinline__ void mma_f16(float* c, uint32_t a0, uint32_t a1,
                                        uint32_t a2, uint32_t a3,
                                        uint32_t b0, uint32_t b1) {
    asm volatile(
        "mma.sync.aligned.m16n8k16.row.col.f32.f16.f16.f32 "
        "{%0,%1,%2,%3}, {%4,%5,%6,%7}, {%8,%9}, {%0,%1,%2,%3};"
        : "+f"(c[0]), "+f"(c[1]), "+f"(c[2]), "+f"(c[3])
        : "r"(a0), "r"(a1), "r"(a2), "r"(a3), "r"(b0), "r"(b1));
}

// ---- fused fp32->bf16 conversion + row squared-norm (one pass) ----
__global__ void cvtnorm_kernel(const float* __restrict__ src,
                               __nv_bfloat16* __restrict__ dst,
                               float* __restrict__ nrm) {
    int row = blockIdx.x;
    const float4* p = reinterpret_cast<const float4*>(src + (size_t)row * DD);
    float4 v = p[threadIdx.x];  // 256 threads x float4 = 1024 elems
    __nv_bfloat162 lo = __floats2bfloat162_rn(v.x, v.y);
    __nv_bfloat162 hi = __floats2bfloat162_rn(v.z, v.w);
    uint2 o;
    o.x = *reinterpret_cast<unsigned*>(&lo);
    o.y = *reinterpret_cast<unsigned*>(&hi);
    reinterpret_cast<uint2*>(dst + (size_t)row * DD)[threadIdx.x] = o;

    float s = fmaf(v.x, v.x, fmaf(v.y, v.y, fmaf(v.z, v.z, v.w * v.w)));
#pragma unroll
    for (int off = 16; off; off >>= 1) s += __shfl_xor_sync(0xffffffffu, s, off);
    __shared__ float ws[8];
    int lane = threadIdx.x & 31, w = threadIdx.x >> 5;
    if (lane == 0) ws[w] = s;
    __syncthreads();
    if (threadIdx.x == 0) {
        float t = 0.f;
#pragma unroll
        for (int i = 0; i < 8; ++i) t += ws[i];
        nrm[row] = t;
    }
}

// ---- transpose W [MM][YY] -> Wt [YY][MM] in fp16 ----
__global__ void wth_kernel(const float* __restrict__ W) {
    __shared__ float t[32][33];
    int bx = blockIdx.x * 32;  // y block
    int by = blockIdx.y * 32;  // m block
    int tx = threadIdx.x, ty = threadIdx.y;
#pragma unroll
    for (int q = 0; q < 4; ++q)
        t[ty + q * 8][tx] = W[(size_t)(by + ty + q * 8) * YY + bx + tx];
    __syncthreads();
#pragma unroll
    for (int q = 0; q < 4; ++q) {
        float v = t[tx][ty + q * 8];
        g_wth[(size_t)(bx + ty + q * 8) * MM + by + tx] = __float2half_rn(v);
    }
}

// ============== GEMM1: bf16 mma.sync, fused Laplacian epilogue ==============
// 128(n) x 256(m) x 64 tile, 512 threads, 16 warps (2x8), warp tile 64x32,
// 3 stages. Fat tile (low L2 traffic) + 16 warps/SM (latency hiding).
#define NCH1 (DD / 64)      // 16
#define S1A (128 * ST1)     // 18432
#define S1B (256 * ST1)     // 36864
#define S1 (S1A + S1B)      // 55296 per stage
#define SMEM1 (3 * S1)      // 165888 (1 CTA/SM, < 228KB)

__device__ __forceinline__ void g1_copy(uint32_t stage, int kc,
                                        int tid, int nBase, int mBase) {
    // A: 128 rows x 128B; 4 threads per row, 2 cp16 each
    {
        int row = tid >> 2;
        int s0 = (tid & 3) * 2;
        const char* asrc = reinterpret_cast<const char*>(g_abf) +
                           ((size_t)(nBase + row) * DD + (size_t)kc * 64) * 2 + s0 * 16;
        uint32_t ad = stage + row * ST1 + s0 * 16;
        cp16(ad, asrc);
        cp16(ad + 16, asrc + 16);
    }
    // B: 256 rows x 128B; 2 threads per row, 4 cp16 each
    {
        int row = tid >> 1;
        int s0 = (tid & 1) * 4;
        int gm = mBase + row;
        if (gm >= MM) gm = MM - 1;  // clamp; epilogue masks stores
        const char* bsrc = reinterpret_cast<const char*>(g_bbf) +
                           ((size_t)gm * DD + (size_t)kc * 64) * 2 + s0 * 16;
        uint32_t bd = stage + S1A + row * ST1 + s0 * 16;
#pragma unroll
        for (int s = 0; s < 4; ++s) cp16(bd + s * 16, bsrc + s * 16);
    }
    cp_commit();
}

__global__ __launch_bounds__(512, 1)
void kmat_mma_kernel(const int* __restrict__ bwp) {
    extern __shared__ __align__(16) char sm1[];

    const int tid = threadIdx.x;
    const int l = tid & 31;
    const int wid = tid >> 5;
    const int wr = wid >> 3;   // 0..1 (n)
    const int wc = wid & 7;    // 0..7 (m)

    // CTA swizzle: groups of 8 n-blocks for L2 reuse
    const int GM = (MM + 255) / 256;  // 79 m-blocks
    int bid = blockIdx.x;
    int grp = bid / (8 * GM);
    int rem = bid % (8 * GM);
    const int nBase = (grp * 8 + (rem & 7)) * 128;
    const int mBase = (rem >> 3) * 256;

    const uint32_t base = s2u(sm1);

    float c[4][4][4];
#pragma unroll
    for (int i = 0; i < 4; ++i)
#pragma unroll
        for (int j = 0; j < 4; ++j)
#pragma unroll
            for (int q = 0; q < 4; ++q) c[i][j][q] = 0.f;

    g1_copy(base + 0 * S1, 0, tid, nBase, mBase);
    g1_copy(base + 1 * S1, 1, tid, nBase, mBase);

    for (int kc = 0; kc < NCH1; ++kc) {
        if (kc < NCH1 - 1) cp_wait<1>(); else cp_wait<0>();
        __syncthreads();
        if (kc + 2 < NCH1)
            g1_copy(base + (uint32_t)((kc + 2) % 3) * S1, kc + 2, tid, nBase, mBase);

        uint32_t aS = base + (uint32_t)(kc % 3) * S1;
        uint32_t bS = aS + S1A;
#pragma unroll
        for (int ks = 0; ks < 4; ++ks) {
            int koff = ks * 32;
            uint32_t a[4][4];
#pragma unroll
            for (int i = 0; i < 4; ++i)
                ldm_x4(a[i][0], a[i][1], a[i][2], a[i][3],
                       aS + (wr * 64 + i * 16 + (l & 15)) * ST1 + koff + ((l >> 4) << 4));
            // B: two j-matrices per ldmatrix.x4 (lane groups 16-31 -> j+1)
            uint32_t b[4][2];
#pragma unroll
            for (int j2 = 0; j2 < 2; ++j2)
                ldm_x4(b[2 * j2][0], b[2 * j2][1], b[2 * j2 + 1][0], b[2 * j2 + 1][1],
                       bS + (wc * 32 + (j2 * 2 + ((l >> 4) & 1)) * 8 + (l & 7)) * ST1 +
                           koff + (((l >> 3) & 1) << 4));
#pragma unroll
            for (int i = 0; i < 4; ++i)
#pragma unroll
                for (int j = 0; j < 4; ++j)
                    mma_bf16(c[i][j], a[i][0], a[i][1], a[i][2], a[i][3],
                             b[j][0], b[j][1]);
        }
    }

    // ---- epilogue: exp(-sqrt(|x|^2+|z|^2-2 dot)/bw) -> fp16 kmat ----
    int ibw = *bwp;
    float bwf = (ibw > 0 && ibw < 1000000) ? (float)ibw : __int_as_float(ibw);
    const float negscale = -1.44269504088896f / bwf;

#pragma unroll
    for (int i = 0; i < 4; ++i) {
        int r0 = nBase + wr * 64 + i * 16 + (l >> 2);
        float xs0 = g_xsq[r0];
        float xs1 = g_xsq[r0 + 8];
#pragma unroll
        for (int j = 0; j < 4; ++j) {
            int col = mBase + wc * 32 + j * 8 + 2 * (l & 3);
            if (col < MM) {  // MM even; a half2 never straddles the edge
                float2 zz = *reinterpret_cast<const float2*>(&g_zsq[col]);
                float d00 = fmaf(-2.f, c[i][j][0], xs0 + zz.x);
                float d01 = fmaf(-2.f, c[i][j][1], xs0 + zz.y);
                float d10 = fmaf(-2.f, c[i][j][2], xs1 + zz.x);
                float d11 = fmaf(-2.f, c[i][j][3], xs1 + zz.y);
                float v00 = ex2_ap(sqrt_ap(fmaxf(d00, 0.f)) * negscale);
                float v01 = ex2_ap(sqrt_ap(fmaxf(d01, 0.f)) * negscale);
                float v10 = ex2_ap(sqrt_ap(fmaxf(d10, 0.f)) * negscale);
                float v11 = ex2_ap(sqrt_ap(fmaxf(d11, 0.f)) * negscale);
                *reinterpret_cast<__half2*>(g_kh + (size_t)r0 * MM + col) =
                    __floats2half2_rn(v00, v01);
                *reinterpret_cast<__half2*>(g_kh + (size_t)(r0 + 8) * MM + col) =
                    __floats2half2_rn(v10, v11);
            }
        }
    }
}

// ============== GEMM2: fp16 mma.sync out = kmat @ W ==============
// 64n x 256y tile, BK=32, 256 threads, 8 warps (2x4), warp 32x64, 4 stages.
#define NCH2 (MM / 32)              // 625
#define S2 ((64 + 256) * ST)        // 25600 B per stage
#define SMEM2 (4 * S2)              // 102400 B

__device__ __forceinline__ void g2_copy(uint32_t stage, int kc,
                                        int tid, int nBase) {
    int s = tid & 3;
    {
        int row = tid >> 2;  // 0..63
        const char* asrc = reinterpret_cast<const char*>(g_kh) +
                           ((size_t)(nBase + row) * MM + (size_t)kc * 32) * 2;
        cp16(stage + row * ST + s * 16, asrc + s * 16);
    }
#pragma unroll
    for (int i = 0; i < 4; ++i) {
        int row = (tid >> 2) + i * 64;  // 0..255 (y)
        const char* bsrc = reinterpret_cast<const char*>(g_wth) +
                           ((size_t)row * MM + (size_t)kc * 32) * 2;
        cp16(stage + 64 * ST + row * ST + s * 16, bsrc + s * 16);
    }
    cp_commit();
}

__global__ __launch_bounds__(256)
void out_mma_kernel(float* __restrict__ Out) {
    extern __shared__ __align__(16) char sm2[];

    const int tid = threadIdx.x;
    const int l = tid & 31;
    const int wid = tid >> 5;
    const int wr = wid >> 2;   // 0..1 (n)
    const int wc = wid & 3;    // 0..3 (y)
    const int nBase = blockIdx.x * 64;
    const uint32_t base = s2u(sm2);

    float c[2][8][4];
#pragma unroll
    for (int i = 0; i < 2; ++i)
#pragma unroll
        for (int j = 0; j < 8; ++j)
#pragma unroll
            for (int q = 0; q < 4; ++q) c[i][j][q] = 0.f;

    g2_copy(base + 0 * S2, 0, tid, nBase);
    g2_copy(base + 1 * S2, 1, tid, nBase);
    g2_copy(base + 2 * S2, 2, tid, nBase);

    for (int kc = 0; kc < NCH2; ++kc) {
        if (kc < NCH2 - 2) cp_wait<2>();
        else if (kc == NCH2 - 2) cp_wait<1>();
        else cp_wait<0>();
        __syncthreads();
        if (kc + 3 < NCH2)
            g2_copy(base + (uint32_t)((kc + 3) & 3) * S2, kc + 3, tid, nBase);

        uint32_t aS = base + (uint32_t)(kc & 3) * S2;
        uint32_t bS = aS + 64 * ST;
#pragma unroll
        for (int ks = 0; ks < 2; ++ks) {
            int koff = ks * 32;
            uint32_t a[2][4];
#pragma unroll
            for (int i = 0; i < 2; ++i)
                ldm_x4(a[i][0], a[i][1], a[i][2], a[i][3],
                       aS + (wr * 32 + i * 16 + (l & 15)) * ST + koff + ((l >> 4) << 4));
            uint32_t b[8][2];
#pragma unroll
            for (int j2 = 0; j2 < 4; ++j2)
                ldm_x4(b[2 * j2][0], b[2 * j2][1], b[2 * j2 + 1][0], b[2 * j2 + 1][1],
                       bS + (wc * 64 + (j2 * 2 + ((l >> 4) & 1)) * 8 + (l & 7)) * ST +
                           koff + (((l >> 3) & 1) << 4));
#pragma unroll
            for (int i = 0; i < 2; ++i)
#pragma unroll
                for (int j = 0; j < 8; ++j)
                    mma_f16(c[i][j], a[i][0], a[i][1], a[i][2], a[i][3],
                            b[j][0], b[j][1]);
        }
    }

#pragma unroll
    for (int i = 0; i < 2; ++i) {
        int r0 = nBase + wr * 32 + i * 16 + (l >> 2);
#pragma unroll
        for (int j = 0; j < 8; ++j) {
            int col = wc * 64 + j * 8 + 2 * (l & 3);
            *reinterpret_cast<float2*>(Out + (size_t)r0 * YY + col) =
                make_float2(c[i][j][0], c[i][j][1]);
            *reinterpret_cast<float2*>(Out + (size_t)(r0 + 8) * YY + col) =
                make_float2(c[i][j][2], c[i][j][3]);
        }
    }
}

extern "C" void kernel_launch(void* const* d_in, const int* in_sizes, int n_in,
                              void* d_out, int out_size) {
    (void)in_sizes; (void)n_in; (void)out_size;
    const float* batch   = (const float*)d_in[0];
    const float* centers = (const float*)d_in[1];
    const float* weight  = (const float*)d_in[2];
    const int*   bwp     = (const int*)d_in[3];
    float* out = (float*)d_out;

    cudaFuncSetAttribute(kmat_mma_kernel,
                         cudaFuncAttributeMaxDynamicSharedMemorySize, SMEM1);
    cudaFuncSetAttribute(out_mma_kernel,
                         cudaFuncAttributeMaxDynamicSharedMemorySize, SMEM2);

    __nv_bfloat16* abf_p = nullptr;
    __nv_bfloat16* bbf_p = nullptr;
    float* xsq_p = nullptr;
    float* zsq_p = nullptr;
    cudaGetSymbolAddress((void**)&abf_p, g_abf);
    cudaGetSymbolAddress((void**)&bbf_p, g_bbf);
    cudaGetSymbolAddress((void**)&xsq_p, g_xsq);
    cudaGetSymbolAddress((void**)&zsq_p, g_zsq);

    cvtnorm_kernel<<<NN, 256>>>(batch, abf_p, xsq_p);
    cvtnorm_kernel<<<MM, 256>>>(centers, bbf_p, zsq_p);

    {
        dim3 b(32, 8);
        dim3 g(YY / 32, MM / 32);  // 8 x 625
        wth_kernel<<<g, b>>>(weight);
    }

    const int GM = (MM + 255) / 256;           // 79
    kmat_mma_kernel<<<GM * (NN / 128), 512, SMEM1>>>(bwp);

    out_mma_kernel<<<NN / 64, 256, SMEM2>>>(out);
}